// round 1
// baseline (speedup 1.0000x reference)
#include <cuda_runtime.h>

#define NGRID 20
#define NPTS  8000          // 20^3
#define TD    39            // offset table dim: offsets -19..19

// Scratch (no device allocation allowed in kernel_launch).
__device__ float g_table[TD * TD * TD];        // ~232 KB Gaussian offset table
__device__ float g_partial[NGRID * NPTS];      // per-ib-slab partial sums
__device__ float g_sum;

// ---------------------------------------------------------------------------
// Kernel 1: build offset table  T[dx+19][dy+19][dz+19] = coef*exp(-0.5 d^T A d)
// ---------------------------------------------------------------------------
__global__ void build_table_kernel(const float* __restrict__ cov_inv) {
    int idx = blockIdx.x * blockDim.x + threadIdx.x;
    if (idx >= TD * TD * TD) return;
    int dz = idx % TD - 19;
    int dy = (idx / TD) % TD - 19;
    int dx = idx / (TD * TD) - 19;
    float a00 = cov_inv[0], a01 = cov_inv[1], a02 = cov_inv[2];
    float a11 = cov_inv[4], a12 = cov_inv[5], a22 = cov_inv[8];
    float fx = (float)dx, fy = (float)dy, fz = (float)dz;
    float d2 = a00 * fx * fx + a11 * fy * fy + a22 * fz * fz
             + 2.0f * (a01 * fx * fy + a02 * fx * fz + a12 * fy * fz);
    d2 = fmaxf(d2, 0.0f);
    g_table[idx] = 0.3989422804014327f * expf(-0.5f * d2);
}

// ---------------------------------------------------------------------------
// Kernel 2: convolution. blockIdx.x = ia (output plane), blockIdx.y = ib
// (input plane). da = ia-ib+19 constant per block -> 6KB table slab in smem.
// 400 threads: thread t owns output (ja = t/20, ka = t%20) within plane ia.
// ---------------------------------------------------------------------------
__global__ void conv_kernel(const float* __restrict__ p) {
    __shared__ float sT[TD * TD];   // T[da, :, :]
    __shared__ float sp[NGRID * NGRID];

    int ia = blockIdx.x;
    int ib = blockIdx.y;
    int da = ia - ib + 19;
    int t  = threadIdx.x;           // 0..399

    const float* Tslab = &g_table[da * TD * TD];
    for (int i = t; i < TD * TD; i += 400) sT[i] = Tslab[i];
    sp[t] = p[ib * 400 + t];
    __syncthreads();

    int ja = t / NGRID;
    int ka = t % NGRID;

    float acc = 0.0f;
    for (int jb = 0; jb < NGRID; jb++) {
        const float* trow = &sT[(ja - jb + 19) * TD + (ka + 19)];
        const float* prow = &sp[jb * NGRID];
#pragma unroll
        for (int kb = 0; kb < NGRID; kb++) {
            // index (ka - kb + 19) in [0, 38]
            acc = fmaf(trow[-kb], prow[kb], acc);
        }
    }
    g_partial[ib * NPTS + ia * 400 + t] = acc;
}

// ---------------------------------------------------------------------------
// Kernel 3: gather partials over the 20 ib slabs -> unnormalized kde in d_out
// ---------------------------------------------------------------------------
__global__ void gather_kernel(float* __restrict__ out) {
    int i = blockIdx.x * blockDim.x + threadIdx.x;
    if (i >= NPTS) return;
    float s = 0.0f;
#pragma unroll
    for (int ib = 0; ib < NGRID; ib++) s += g_partial[ib * NPTS + i];
    out[i] = s;
}

// ---------------------------------------------------------------------------
// Kernel 4: deterministic total sum (single block, fixed-order tree reduce)
// ---------------------------------------------------------------------------
__global__ void reduce_kernel(const float* __restrict__ out) {
    __shared__ float ssum[1024];
    int t = threadIdx.x;
    float s = 0.0f;
    for (int i = t; i < NPTS; i += 1024) s += out[i];
    ssum[t] = s;
    __syncthreads();
    for (int k = 512; k > 0; k >>= 1) {
        if (t < k) ssum[t] += ssum[t + k];
        __syncthreads();
    }
    if (t == 0) g_sum = ssum[0];
}

// ---------------------------------------------------------------------------
// Kernel 5: normalize
// ---------------------------------------------------------------------------
__global__ void scale_kernel(float* __restrict__ out) {
    int i = blockIdx.x * blockDim.x + threadIdx.x;
    if (i >= NPTS) return;
    out[i] = out[i] / g_sum;
}

extern "C" void kernel_launch(void* const* d_in, const int* in_sizes, int n_in,
                              void* d_out, int out_size) {
    const float* space_probs = (const float*)d_in[0];  // 8000 floats
    const float* cov_inv     = (const float*)d_in[1];  // 9 floats
    float* out = (float*)d_out;                        // 8000 floats

    build_table_kernel<<<(TD * TD * TD + 255) / 256, 256>>>(cov_inv);
    conv_kernel<<<dim3(NGRID, NGRID), 400>>>(space_probs);
    gather_kernel<<<(NPTS + 255) / 256, 256>>>(out);
    reduce_kernel<<<1, 1024>>>(out);
    scale_kernel<<<(NPTS + 255) / 256, 256>>>(out);
}

// round 2
// speedup vs baseline: 1.9907x; 1.9907x over previous
#include <cuda_runtime.h>

#define NGRID 20
#define NPTS  8000           // 20^3
#define TD    39             // offsets -19..19
#define DA_MAX 9             // prune |ia-ib| > 9  (min d2 = da^2/COV00 > 40 -> w < 2e-9)
#define D2_CUT 40.0f

// Scratch (no allocation allowed in kernel_launch)
__device__ float g_partial[NGRID * NPTS];   // [ib][pt]
__device__ float g_bsum[8];

// ---------------------------------------------------------------------------
// Kernel A: fused table-build + conv.
// grid (5, 20): blockIdx.x -> ia group of 4 planes, blockIdx.y -> ib plane.
// 400 threads: q = t/100 picks the ia plane, then (ja, ka0=4*kq) within it;
// each thread produces 4 outputs (ka0..ka0+3) via a sliding register window
// over the shared table row -> ~0.35 LDS per FFMA instead of 2.
// ---------------------------------------------------------------------------
__global__ void __launch_bounds__(400) conv_kernel(
    const float* __restrict__ p, const float* __restrict__ cov_inv)
{
    __shared__ float sT[4 * TD * TD];     // 4 table slabs (one per ia plane)
    __shared__ float sp[NGRID * NGRID];   // input plane ib

    const int t   = threadIdx.x;
    const int ib  = blockIdx.y;
    const int ia0 = blockIdx.x * 4;

    // Uniform block-level prune: min over q of |ia0+q-ib| > DA_MAX
    {
        int lo = ia0 - ib, hi = ia0 + 3 - ib;
        int mind = (lo > 0) ? lo : ((hi < 0) ? -hi : 0);
        if (mind > DA_MAX) return;
    }

    const float a00 = cov_inv[0], a01 = cov_inv[1], a02 = cov_inv[2];
    const float a11 = cov_inv[4], a12 = cov_inv[5], a22 = cov_inv[8];

    sp[t] = p[ib * 400 + t];

    // Build the (up to) 4 needed slabs: T[da][dy+19][dz+19]
    for (int e = t; e < 4 * TD * TD; e += 400) {
        int q   = e / (TD * TD);
        int rem = e - q * TD * TD;
        int da  = ia0 + q - ib;
        if (da < -DA_MAX || da > DA_MAX) continue;   // slab never read
        float fx = (float)da;
        float fy = (float)(rem / TD - 19);
        float fz = (float)(rem - (rem / TD) * TD - 19);
        float d2 = a00 * fx * fx + a11 * fy * fy + a22 * fz * fz
                 + 2.0f * (a01 * fx * fy + a02 * fx * fz + a12 * fy * fz);
        sT[e] = 0.3989422804014327f * expf(-0.5f * fmaxf(d2, 0.0f));
    }
    __syncthreads();

    const int q    = t / 100;
    const int ia   = ia0 + q;
    const int da   = ia - ib;
    const int r100 = t - q * 100;
    const int ja   = r100 / 5;
    const int ka0  = (r100 - ja * 5) * 4;

    if (da < -DA_MAX || da > DA_MAX) return;   // this plane pruned

    // Per-thread jb range from 2D Schur complement (min over dz of d2):
    // s00*dx^2 + 2*s01*dx*dy + s11*dy^2 <= D2_CUT, dy = ja - jb
    float s00 = a00 - a02 * a02 / a22;
    float s01 = a01 - a02 * a12 / a22;
    float s11 = a11 - a12 * a12 / a22;
    float fx  = (float)da;
    float bq  = s01 * fx;
    float disc = bq * bq - s11 * (s00 * fx * fx - D2_CUT);
    int jb_lo = 0, jb_hi = -1;
    if (disc > 0.0f) {
        float sq  = sqrtf(disc);
        float dyl = (-bq - sq) / s11;
        float dyh = (-bq + sq) / s11;
        jb_lo = max(0,  (int)ceilf ((float)ja - dyh - 0.01f));
        jb_hi = min(19, (int)floorf((float)ja - dyl + 0.01f));
    }

    float acc0 = 0.f, acc1 = 0.f, acc2 = 0.f, acc3 = 0.f;
    const float* slab = &sT[q * TD * TD];

    for (int jb = jb_lo; jb <= jb_hi; jb++) {
        const float* row = slab + (ja - jb + 19) * TD;

        float pv[20];
        {
            const float4* pr4 = reinterpret_cast<const float4*>(&sp[jb * NGRID]);
#pragma unroll
            for (int u = 0; u < 5; u++) {
                float4 v = pr4[u];
                pv[4*u] = v.x; pv[4*u+1] = v.y; pv[4*u+2] = v.z; pv[4*u+3] = v.w;
            }
        }

        // sliding window: w_r(kb) = row[ka0 + r + 19 - kb]
        float w0 = row[ka0 + 19];
        float w1 = row[ka0 + 20];
        float w2 = row[ka0 + 21];
        float w3 = row[ka0 + 22];
#pragma unroll
        for (int kb = 0; kb < 20; kb++) {
            float pvk = pv[kb];
            acc0 = fmaf(w0, pvk, acc0);
            acc1 = fmaf(w1, pvk, acc1);
            acc2 = fmaf(w2, pvk, acc2);
            acc3 = fmaf(w3, pvk, acc3);
            if (kb < 19) { w3 = w2; w2 = w1; w1 = w0; w0 = row[ka0 + 18 - kb]; }
        }
    }

    int pt = ia * 400 + ja * 20 + ka0;      // pt % 4 == 0 -> aligned float4 store
    *reinterpret_cast<float4*>(&g_partial[ib * NPTS + pt]) =
        make_float4(acc0, acc1, acc2, acc3);
}

// ---------------------------------------------------------------------------
// Kernel B: gather partials (same |ia-ib|<=DA_MAX rule) -> unnormalized out,
// plus per-block sums for the normalizer. 8 blocks x 1024 threads.
// ---------------------------------------------------------------------------
__global__ void __launch_bounds__(1024) gather_kernel(float* __restrict__ out) {
    __shared__ float red[1024];
    int pt = blockIdx.x * 1024 + threadIdx.x;
    float s = 0.0f;
    if (pt < NPTS) {
        int ia = pt / 400;
        int lo = max(0, ia - DA_MAX), hi = min(19, ia + DA_MAX);
        for (int ib = lo; ib <= hi; ib++) s += g_partial[ib * NPTS + pt];
        out[pt] = s;
    }
    red[threadIdx.x] = s;
    __syncthreads();
    for (int k = 512; k > 0; k >>= 1) {
        if (threadIdx.x < k) red[threadIdx.x] += red[threadIdx.x + k];
        __syncthreads();
    }
    if (threadIdx.x == 0) g_bsum[blockIdx.x] = red[0];
}

// ---------------------------------------------------------------------------
// Kernel C: normalize. Each thread folds the 8 block sums (fixed order ->
// deterministic) and divides.
// ---------------------------------------------------------------------------
__global__ void __launch_bounds__(1024) scale_kernel(float* __restrict__ out) {
    float S = 0.0f;
#pragma unroll
    for (int i = 0; i < 8; i++) S += g_bsum[i];
    int pt = blockIdx.x * 1024 + threadIdx.x;
    if (pt < NPTS) out[pt] = out[pt] / S;
}

extern "C" void kernel_launch(void* const* d_in, const int* in_sizes, int n_in,
                              void* d_out, int out_size) {
    const float* space_probs = (const float*)d_in[0];  // 8000 floats
    const float* cov_inv     = (const float*)d_in[1];  // 9 floats
    float* out = (float*)d_out;                        // 8000 floats

    conv_kernel  <<<dim3(5, 20), 400>>>(space_probs, cov_inv);
    gather_kernel<<<8, 1024>>>(out);
    scale_kernel <<<8, 1024>>>(out);
}

// round 4
// speedup vs baseline: 2.4951x; 1.2534x over previous
#include <cuda_runtime.h>

#define NGRID 20
#define NPTS  8000           // 20^3
#define TD    39             // offsets -19..19
#define DA_MAX 9             // |ia-ib| > 9 -> min d2 > 40 -> weight < 2e-9
#define D2_CUT 40.0f

// Scratch (no allocation allowed in kernel_launch)
__device__ float g_partial[NGRID * NPTS];   // [ib][pt]
__device__ float g_bsum[NGRID * NGRID];     // per (ia,ib) block sum

// ---------------------------------------------------------------------------
// Kernel A: one (ia, ib) pair per block. 400 threads = 100 output-threads
// (4 outputs each, sliding table window) x 4 jb-split groups. Table slab for
// the single da is built with a 2-FMUL exp recurrence. Block also reduces its
// own contribution to the global normalizer into g_bsum.
// ---------------------------------------------------------------------------
__global__ void __launch_bounds__(400) conv_kernel(
    const float* __restrict__ p, const float* __restrict__ cov_inv)
{
    // All 16B-aligned: sp and sred see float4 accesses.
    __shared__ __align__(16) float sT[TD * TD + 3];   // pad to multiple of 4
    __shared__ __align__(16) float sp[NGRID * NGRID];
    __shared__ __align__(16) float sred[1600];

    const int t  = threadIdx.x;
    const int ia = blockIdx.x;
    const int ib = blockIdx.y;
    const int da = ia - ib;

    if (da < -DA_MAX || da > DA_MAX) {
        if (t == 0) g_bsum[ia * NGRID + ib] = 0.0f;
        return;
    }

    const float a00 = cov_inv[0], a01 = cov_inv[1], a02 = cov_inv[2];
    const float a11 = cov_inv[4], a12 = cov_inv[5], a22 = cov_inv[8];

    sp[t] = p[ib * 400 + t];

    // Table build: thread t<156 handles row (t>>2), segment (t&3) of 10|10|10|9.
    // g(dz+1) = g(dz)*r(dz), r(dz+1) = r(dz)*B  with B = exp(-a22).
    if (t < 156) {
        int row = t >> 2, seg = t & 3;
        float dy = (float)(row - 19);
        int   dz0 = -19 + seg * 10;
        int   cnt = (seg == 3) ? 9 : 10;
        float dx = (float)da;
        float c1 = 2.0f * (a02 * dx + a12 * dy);
        float c0 = a00 * dx * dx + 2.0f * a01 * dx * dy + a11 * dy * dy;
        float z  = (float)dz0;
        float g  = expf(-0.5f * (c0 + c1 * z + a22 * z * z));
        float r  = expf(-0.5f * (c1 + a22 * (2.0f * z + 1.0f)));
        float B  = expf(-a22);
        float* dst = &sT[row * TD + (dz0 + 19)];
        for (int i = 0; i < cnt; i++) { dst[i] = g; g *= r; r *= B; }
    }
    __syncthreads();

    const int gidx = t / 100;           // jb-split group 0..3
    const int s    = t - gidx * 100;    // output slot 0..99
    const int ja   = s / 5;
    const int ka0  = (s - ja * 5) * 4;

    // Per-thread jb range via 2D Schur complement (min over dz of d2)
    float s00 = a00 - a02 * a02 / a22;
    float s01 = a01 - a02 * a12 / a22;
    float s11 = a11 - a12 * a12 / a22;
    float fx  = (float)da;
    float bq  = s01 * fx;
    float disc = bq * bq - s11 * (s00 * fx * fx - D2_CUT);
    int jb_lo = 0, jb_hi = -1;
    if (disc > 0.0f) {
        float sq  = sqrtf(disc);
        float dyl = (-bq - sq) / s11;
        float dyh = (-bq + sq) / s11;
        jb_lo = max(0,  (int)ceilf ((float)ja - dyh - 0.01f));
        jb_hi = min(19, (int)floorf((float)ja - dyl + 0.01f));
    }

    float acc0 = 0.f, acc1 = 0.f, acc2 = 0.f, acc3 = 0.f;

    for (int jb = jb_lo + gidx; jb <= jb_hi; jb += 4) {
        const float* row = &sT[(ja - jb + 19) * TD];

        float pv[20];
        {
            const float4* pr4 = reinterpret_cast<const float4*>(&sp[jb * NGRID]);
#pragma unroll
            for (int u = 0; u < 5; u++) {
                float4 v = pr4[u];
                pv[4*u] = v.x; pv[4*u+1] = v.y; pv[4*u+2] = v.z; pv[4*u+3] = v.w;
            }
        }

        float w0 = row[ka0 + 19];
        float w1 = row[ka0 + 20];
        float w2 = row[ka0 + 21];
        float w3 = row[ka0 + 22];
#pragma unroll
        for (int kb = 0; kb < 20; kb++) {
            float pvk = pv[kb];
            acc0 = fmaf(w0, pvk, acc0);
            acc1 = fmaf(w1, pvk, acc1);
            acc2 = fmaf(w2, pvk, acc2);
            acc3 = fmaf(w3, pvk, acc3);
            if (kb < 19) { w3 = w2; w2 = w1; w1 = w0; w0 = row[ka0 + 18 - kb]; }
        }
    }

    // output index o = s*4 + r  (== ja*20 + ka0 + r)
    *reinterpret_cast<float4*>(&sred[gidx * 400 + s * 4]) =
        make_float4(acc0, acc1, acc2, acc3);
    __syncthreads();

    // fold the 4 jb-groups in fixed order, write partial plane
    float val = sred[t] + sred[400 + t] + sred[800 + t] + sred[1200 + t];
    g_partial[ib * NPTS + ia * 400 + t] = val;
    __syncthreads();

    // block sum (deterministic tree over 512 padded entries)
    sred[t] = val;
    if (t < 112) sred[400 + t] = 0.0f;
    __syncthreads();
    for (int k = 256; k > 32; k >>= 1) {
        if (t < k) sred[t] += sred[t + k];
        __syncthreads();
    }
    if (t < 32) {
        float v = sred[t] + sred[t + 32];
#pragma unroll
        for (int off = 16; off > 0; off >>= 1)
            v += __shfl_down_sync(0xffffffffu, v, off);
        if (t == 0) g_bsum[ia * NGRID + ib] = v;
    }
}

// ---------------------------------------------------------------------------
// Kernel B: fold the 400 block sums (fixed order) -> S, gather ib-window
// partials -> kde, write kde/S. 8 blocks x 1024 threads, one pass.
// ---------------------------------------------------------------------------
__global__ void __launch_bounds__(1024) finish_kernel(float* __restrict__ out) {
    __shared__ float sb[512];
    int t = threadIdx.x;
    if (t < 512) sb[t] = (t < 400) ? g_bsum[t] : 0.0f;
    __syncthreads();
    for (int k = 256; k > 0; k >>= 1) {
        if (t < k) sb[t] += sb[t + k];
        __syncthreads();
    }
    float S = sb[0];

    int pt = blockIdx.x * 1024 + t;
    if (pt < NPTS) {
        int ia = pt / 400;
        int lo = max(0, ia - DA_MAX), hi = min(19, ia + DA_MAX);
        float s = 0.0f;
        for (int ib = lo; ib <= hi; ib++) s += g_partial[ib * NPTS + pt];
        out[pt] = s / S;
    }
}

extern "C" void kernel_launch(void* const* d_in, const int* in_sizes, int n_in,
                              void* d_out, int out_size) {
    const float* space_probs = (const float*)d_in[0];  // 8000 floats
    const float* cov_inv     = (const float*)d_in[1];  // 9 floats
    float* out = (float*)d_out;                        // 8000 floats

    conv_kernel  <<<dim3(NGRID, NGRID), 400>>>(space_probs, cov_inv);
    finish_kernel<<<8, 1024>>>(out);
}

// round 6
// speedup vs baseline: 3.1527x; 1.2635x over previous
#include <cuda_runtime.h>

#define NGRID 20
#define NPTS  8000           // 20^3
#define TD    39             // offsets -19..19
#define DA_MAX 9             // |ia-ib| > 9 -> min d2 > 40 -> weight < 2e-9
#define D2_CUT 40.0f

// Scratch (no allocation allowed in kernel_launch)
__device__ float g_partial[NGRID * NPTS];   // [ib][pt]
__device__ float g_bsum[NGRID * NGRID];     // per (ia,ib) block sum

// ---------------------------------------------------------------------------
// Kernel A: one (ia, ib) pair per block. 400 threads = 100 output-threads
// (4 outputs each, sliding table window) x 4 jb-split groups. Table slab for
// the single da is built with a 2-FMUL exp recurrence. Block also reduces its
// own contribution to the global normalizer into g_bsum.  (UNCHANGED from R4
// — measured ~3us, met prediction.)
// ---------------------------------------------------------------------------
__global__ void __launch_bounds__(400) conv_kernel(
    const float* __restrict__ p, const float* __restrict__ cov_inv)
{
    __shared__ __align__(16) float sT[TD * TD + 3];
    __shared__ __align__(16) float sp[NGRID * NGRID];
    __shared__ __align__(16) float sred[1600];

    const int t  = threadIdx.x;
    const int ia = blockIdx.x;
    const int ib = blockIdx.y;
    const int da = ia - ib;

    if (da < -DA_MAX || da > DA_MAX) {
        if (t == 0) g_bsum[ia * NGRID + ib] = 0.0f;
        return;
    }

    const float a00 = cov_inv[0], a01 = cov_inv[1], a02 = cov_inv[2];
    const float a11 = cov_inv[4], a12 = cov_inv[5], a22 = cov_inv[8];

    sp[t] = p[ib * 400 + t];

    if (t < 156) {
        int row = t >> 2, seg = t & 3;
        float dy = (float)(row - 19);
        int   dz0 = -19 + seg * 10;
        int   cnt = (seg == 3) ? 9 : 10;
        float dx = (float)da;
        float c1 = 2.0f * (a02 * dx + a12 * dy);
        float c0 = a00 * dx * dx + 2.0f * a01 * dx * dy + a11 * dy * dy;
        float z  = (float)dz0;
        float g  = expf(-0.5f * (c0 + c1 * z + a22 * z * z));
        float r  = expf(-0.5f * (c1 + a22 * (2.0f * z + 1.0f)));
        float B  = expf(-a22);
        float* dst = &sT[row * TD + (dz0 + 19)];
        for (int i = 0; i < cnt; i++) { dst[i] = g; g *= r; r *= B; }
    }
    __syncthreads();

    const int gidx = t / 100;
    const int s    = t - gidx * 100;
    const int ja   = s / 5;
    const int ka0  = (s - ja * 5) * 4;

    float s00 = a00 - a02 * a02 / a22;
    float s01 = a01 - a02 * a12 / a22;
    float s11 = a11 - a12 * a12 / a22;
    float fx  = (float)da;
    float bq  = s01 * fx;
    float disc = bq * bq - s11 * (s00 * fx * fx - D2_CUT);
    int jb_lo = 0, jb_hi = -1;
    if (disc > 0.0f) {
        float sq  = sqrtf(disc);
        float dyl = (-bq - sq) / s11;
        float dyh = (-bq + sq) / s11;
        jb_lo = max(0,  (int)ceilf ((float)ja - dyh - 0.01f));
        jb_hi = min(19, (int)floorf((float)ja - dyl + 0.01f));
    }

    float acc0 = 0.f, acc1 = 0.f, acc2 = 0.f, acc3 = 0.f;

    for (int jb = jb_lo + gidx; jb <= jb_hi; jb += 4) {
        const float* row = &sT[(ja - jb + 19) * TD];

        float pv[20];
        {
            const float4* pr4 = reinterpret_cast<const float4*>(&sp[jb * NGRID]);
#pragma unroll
            for (int u = 0; u < 5; u++) {
                float4 v = pr4[u];
                pv[4*u] = v.x; pv[4*u+1] = v.y; pv[4*u+2] = v.z; pv[4*u+3] = v.w;
            }
        }

        float w0 = row[ka0 + 19];
        float w1 = row[ka0 + 20];
        float w2 = row[ka0 + 21];
        float w3 = row[ka0 + 22];
#pragma unroll
        for (int kb = 0; kb < 20; kb++) {
            float pvk = pv[kb];
            acc0 = fmaf(w0, pvk, acc0);
            acc1 = fmaf(w1, pvk, acc1);
            acc2 = fmaf(w2, pvk, acc2);
            acc3 = fmaf(w3, pvk, acc3);
            if (kb < 19) { w3 = w2; w2 = w1; w1 = w0; w0 = row[ka0 + 18 - kb]; }
        }
    }

    *reinterpret_cast<float4*>(&sred[gidx * 400 + s * 4]) =
        make_float4(acc0, acc1, acc2, acc3);
    __syncthreads();

    float val = sred[t] + sred[400 + t] + sred[800 + t] + sred[1200 + t];
    g_partial[ib * NPTS + ia * 400 + t] = val;
    __syncthreads();

    sred[t] = val;
    if (t < 112) sred[400 + t] = 0.0f;
    __syncthreads();
    for (int k = 256; k > 32; k >>= 1) {
        if (t < k) sred[t] += sred[t + k];
        __syncthreads();
    }
    if (t < 32) {
        float v = sred[t] + sred[t + 32];
#pragma unroll
        for (int off = 16; off > 0; off >>= 1)
            v += __shfl_down_sync(0xffffffffu, v, off);
        if (t == 0) g_bsum[ia * NGRID + ib] = v;
    }
}

// ---------------------------------------------------------------------------
// Kernel B (reworked): 32 blocks x 256 threads, one grid point per thread.
// Fixed-trip unrolled gather (19 predicated loads -> high MLP), fixed-order
// fold of the 400 block sums, single write of kde/S.
// ---------------------------------------------------------------------------
__global__ void __launch_bounds__(256) finish_kernel(float* __restrict__ out) {
    __shared__ float sb[256];
    const int t = threadIdx.x;

    // Fold 400 block sums -> S (fixed order, deterministic)
    float v = 0.0f;
    if (t < 200) v = g_bsum[t] + g_bsum[t + 200];
    sb[t] = v;
    __syncthreads();
    for (int k = 128; k > 0; k >>= 1) {
        if (t < k) sb[t] += sb[t + k];
        __syncthreads();
    }
    const float S = sb[0];

    const int pt = blockIdx.x * 256 + t;
    if (pt >= NPTS) return;

    const int ia = pt / 400;
    const int lo = max(0, ia - DA_MAX);
    const int hi = min(19, ia + DA_MAX);

    float s = 0.0f;
#pragma unroll
    for (int k = 0; k < 2 * DA_MAX + 1; k++) {   // 19 predicated, batched loads
        int ib = lo + k;
        if (ib <= hi) s += g_partial[ib * NPTS + pt];
    }
    out[pt] = s / S;
}

extern "C" void kernel_launch(void* const* d_in, const int* in_sizes, int n_in,
                              void* d_out, int out_size) {
    const float* space_probs = (const float*)d_in[0];  // 8000 floats
    const float* cov_inv     = (const float*)d_in[1];  // 9 floats
    float* out = (float*)d_out;                        // 8000 floats

    conv_kernel  <<<dim3(NGRID, NGRID), 400>>>(space_probs, cov_inv);
    finish_kernel<<<32, 256>>>(out);
}

// round 7
// speedup vs baseline: 3.2653x; 1.0357x over previous
#include <cuda_runtime.h>

#define NGRID 20
#define NPTS  8000           // 20^3
#define TD    39             // offsets -19..19
#define DA_MAX 9             // |ia-ib| > 9 -> min d2 > 40 -> weight < 2e-9
#define D2_CUT 40.0f

// Scratch (no allocation allowed in kernel_launch)
__device__ float g_partial[NGRID * NPTS];   // [ib][pt]
__device__ float g_bsum[NGRID * NGRID];     // per (ia,ib) block sum

// ---------------------------------------------------------------------------
// Kernel A: one (ia, ib) pair per block. 400 threads = 100 output-threads
// (4 outputs each, sliding table window) x 4 jb-split groups. Table slab for
// the single da is built with a 2-FMUL exp recurrence. Block also reduces its
// own contribution to the global normalizer into g_bsum.  (FROZEN — met
// prediction in R4/R6.)
// ---------------------------------------------------------------------------
__global__ void __launch_bounds__(400) conv_kernel(
    const float* __restrict__ p, const float* __restrict__ cov_inv)
{
    __shared__ __align__(16) float sT[TD * TD + 3];
    __shared__ __align__(16) float sp[NGRID * NGRID];
    __shared__ __align__(16) float sred[1600];

    const int t  = threadIdx.x;
    const int ia = blockIdx.x;
    const int ib = blockIdx.y;
    const int da = ia - ib;

    if (da < -DA_MAX || da > DA_MAX) {
        if (t == 0) g_bsum[ia * NGRID + ib] = 0.0f;
        return;
    }

    const float a00 = cov_inv[0], a01 = cov_inv[1], a02 = cov_inv[2];
    const float a11 = cov_inv[4], a12 = cov_inv[5], a22 = cov_inv[8];

    sp[t] = p[ib * 400 + t];

    if (t < 156) {
        int row = t >> 2, seg = t & 3;
        float dy = (float)(row - 19);
        int   dz0 = -19 + seg * 10;
        int   cnt = (seg == 3) ? 9 : 10;
        float dx = (float)da;
        float c1 = 2.0f * (a02 * dx + a12 * dy);
        float c0 = a00 * dx * dx + 2.0f * a01 * dx * dy + a11 * dy * dy;
        float z  = (float)dz0;
        float g  = expf(-0.5f * (c0 + c1 * z + a22 * z * z));
        float r  = expf(-0.5f * (c1 + a22 * (2.0f * z + 1.0f)));
        float B  = expf(-a22);
        float* dst = &sT[row * TD + (dz0 + 19)];
        for (int i = 0; i < cnt; i++) { dst[i] = g; g *= r; r *= B; }
    }
    __syncthreads();

    const int gidx = t / 100;
    const int s    = t - gidx * 100;
    const int ja   = s / 5;
    const int ka0  = (s - ja * 5) * 4;

    float s00 = a00 - a02 * a02 / a22;
    float s01 = a01 - a02 * a12 / a22;
    float s11 = a11 - a12 * a12 / a22;
    float fx  = (float)da;
    float bq  = s01 * fx;
    float disc = bq * bq - s11 * (s00 * fx * fx - D2_CUT);
    int jb_lo = 0, jb_hi = -1;
    if (disc > 0.0f) {
        float sq  = sqrtf(disc);
        float dyl = (-bq - sq) / s11;
        float dyh = (-bq + sq) / s11;
        jb_lo = max(0,  (int)ceilf ((float)ja - dyh - 0.01f));
        jb_hi = min(19, (int)floorf((float)ja - dyl + 0.01f));
    }

    float acc0 = 0.f, acc1 = 0.f, acc2 = 0.f, acc3 = 0.f;

    for (int jb = jb_lo + gidx; jb <= jb_hi; jb += 4) {
        const float* row = &sT[(ja - jb + 19) * TD];

        float pv[20];
        {
            const float4* pr4 = reinterpret_cast<const float4*>(&sp[jb * NGRID]);
#pragma unroll
            for (int u = 0; u < 5; u++) {
                float4 v = pr4[u];
                pv[4*u] = v.x; pv[4*u+1] = v.y; pv[4*u+2] = v.z; pv[4*u+3] = v.w;
            }
        }

        float w0 = row[ka0 + 19];
        float w1 = row[ka0 + 20];
        float w2 = row[ka0 + 21];
        float w3 = row[ka0 + 22];
#pragma unroll
        for (int kb = 0; kb < 20; kb++) {
            float pvk = pv[kb];
            acc0 = fmaf(w0, pvk, acc0);
            acc1 = fmaf(w1, pvk, acc1);
            acc2 = fmaf(w2, pvk, acc2);
            acc3 = fmaf(w3, pvk, acc3);
            if (kb < 19) { w3 = w2; w2 = w1; w1 = w0; w0 = row[ka0 + 18 - kb]; }
        }
    }

    *reinterpret_cast<float4*>(&sred[gidx * 400 + s * 4]) =
        make_float4(acc0, acc1, acc2, acc3);
    __syncthreads();

    float val = sred[t] + sred[400 + t] + sred[800 + t] + sred[1200 + t];
    g_partial[ib * NPTS + ia * 400 + t] = val;
    __syncthreads();

    sred[t] = val;
    if (t < 112) sred[400 + t] = 0.0f;
    __syncthreads();
    for (int k = 256; k > 32; k >>= 1) {
        if (t < k) sred[t] += sred[t + k];
        __syncthreads();
    }
    if (t < 32) {
        float v = sred[t] + sred[t + 32];
#pragma unroll
        for (int off = 16; off > 0; off >>= 1)
            v += __shfl_down_sync(0xffffffffu, v, off);
        if (t == 0) g_bsum[ia * NGRID + ib] = v;
    }
}

// ---------------------------------------------------------------------------
// Kernel B (reworked again): 64 blocks x 128 threads, one point per thread.
// Gather loads issued FIRST; S folded barrier-free by every warp redundantly
// (13 predicated strided loads + shfl tree, fixed order -> deterministic and
// identical across warps). Loads of g_bsum overlap the gather loads.
// ---------------------------------------------------------------------------
__global__ void __launch_bounds__(128) finish_kernel(float* __restrict__ out) {
    const int t    = threadIdx.x;
    const int lane = t & 31;
    const int pt   = blockIdx.x * 128 + t;

    // --- issue gather loads first (independent of S) ---
    const int ia = (pt < NPTS) ? (pt / 400) : 0;
    const int lo = max(0, ia - DA_MAX);
    const int hi = min(19, ia + DA_MAX);

    float gv[2 * DA_MAX + 1];
#pragma unroll
    for (int k = 0; k < 2 * DA_MAX + 1; k++) {
        int ib = lo + k;
        gv[k] = (pt < NPTS && ib <= hi) ? g_partial[ib * NPTS + pt] : 0.0f;
    }

    // --- warp-redundant fold of 400 block sums (no __syncthreads) ---
    float v = 0.0f;
#pragma unroll
    for (int i = 0; i < 13; i++) {            // 13*32 = 416 >= 400
        int idx = lane + 32 * i;
        if (idx < 400) v += g_bsum[idx];
    }
#pragma unroll
    for (int off = 16; off > 0; off >>= 1)
        v += __shfl_xor_sync(0xffffffffu, v, off);   // butterfly: all lanes get S
    const float S = v;

    if (pt >= NPTS) return;

    float s = 0.0f;
#pragma unroll
    for (int k = 0; k < 2 * DA_MAX + 1; k++) s += gv[k];
    out[pt] = s / S;
}

extern "C" void kernel_launch(void* const* d_in, const int* in_sizes, int n_in,
                              void* d_out, int out_size) {
    const float* space_probs = (const float*)d_in[0];  // 8000 floats
    const float* cov_inv     = (const float*)d_in[1];  // 9 floats
    float* out = (float*)d_out;                        // 8000 floats

    conv_kernel  <<<dim3(NGRID, NGRID), 400>>>(space_probs, cov_inv);
    finish_kernel<<<64, 128>>>(out);
}